// round 2
// baseline (speedup 1.0000x reference)
#include <cuda_runtime.h>
#include <cuda_bf16.h>
#include <math.h>

// ---------------------------------------------------------------------------
// Problem constants
// B=2, S=2048, D=2048, H=16, NOPE=128, ROPE=64, DV=128, DQK=192
// QLR=1536, KVLR=512
// tokens T = B*S = 4096
// ---------------------------------------------------------------------------
#define TOK 4096
#define SEQ 2048
#define NH 16
#define DQK 192
#define DV 128

// ---------------------------------------------------------------------------
// Device scratch (static, allocation-free)
// ---------------------------------------------------------------------------
__device__ float g_qlat [4096 * 1536];          // q latent (rmsnormed in place)
__device__ float g_kvdr [4096 * 576];           // kv down raw
__device__ float g_kvlat[4096 * 512];           // rmsnormed kv latent
__device__ float g_krope[4096 * 64];            // roped k_rope per token
__device__ float g_qraw [4096L * 3072];         // q up-proj raw
__device__ float g_kv   [4096L * 4096];         // kv up-proj
__device__ float g_q    [32L * 2048 * 192];     // [b*H+h][s][192]
__device__ float g_k    [32L * 2048 * 192];
__device__ float g_v    [32L * 2048 * 128];
__device__ float g_attn [4096L * 2048];         // attention output, head-major cols

// ---------------------------------------------------------------------------
// Generic fp32 GEMM: C[M,N] = A[M,K] @ B[K,N], row-major.
// 128x128 block tile, BK=16, 256 threads, 8x8 per-thread micro-tile.
// Requires: M % 128 == 0, K % 16 == 0, N % 4 == 0. N guard on loads/stores.
// ---------------------------------------------------------------------------
__global__ __launch_bounds__(256) void gemm_kernel(
    const float* __restrict__ A, const float* __restrict__ B,
    float* __restrict__ C, int M, int N, int K)
{
    __shared__ float As[16][128];
    __shared__ float Bs[16][128];

    const int tid = threadIdx.x;
    const int tx = tid & 15;
    const int ty = tid >> 4;
    const int row0 = blockIdx.y * 128;
    const int col0 = blockIdx.x * 128;

    const int arow = tid >> 2;          // 0..63
    const int acol = (tid & 3) << 2;    // 0,4,8,12
    const int brow = tid >> 5;          // 0..7
    const int bcol = (tid & 31) << 2;   // 0..124

    float acc[8][8];
#pragma unroll
    for (int i = 0; i < 8; i++)
#pragma unroll
        for (int j = 0; j < 8; j++) acc[i][j] = 0.f;

    for (int k0 = 0; k0 < K; k0 += 16) {
#pragma unroll
        for (int p = 0; p < 2; p++) {
            int r = arow + p * 64;
            const float4 va = *(const float4*)&A[(size_t)(row0 + r) * K + k0 + acol];
            As[acol + 0][r] = va.x;
            As[acol + 1][r] = va.y;
            As[acol + 2][r] = va.z;
            As[acol + 3][r] = va.w;
        }
#pragma unroll
        for (int p = 0; p < 2; p++) {
            int r = brow + p * 8;
            int c = col0 + bcol;
            float4 vb = make_float4(0.f, 0.f, 0.f, 0.f);
            if (c < N) vb = *(const float4*)&B[(size_t)(k0 + r) * N + c];
            *(float4*)&Bs[r][bcol] = vb;
        }
        __syncthreads();

#pragma unroll
        for (int kk = 0; kk < 16; kk++) {
            const float4 a0 = *(const float4*)&As[kk][ty * 4];
            const float4 a1 = *(const float4*)&As[kk][ty * 4 + 64];
            const float4 b0 = *(const float4*)&Bs[kk][tx * 4];
            const float4 b1 = *(const float4*)&Bs[kk][tx * 4 + 64];
            const float av[8] = {a0.x, a0.y, a0.z, a0.w, a1.x, a1.y, a1.z, a1.w};
            const float bv[8] = {b0.x, b0.y, b0.z, b0.w, b1.x, b1.y, b1.z, b1.w};
#pragma unroll
            for (int i = 0; i < 8; i++)
#pragma unroll
                for (int j = 0; j < 8; j++)
                    acc[i][j] += av[i] * bv[j];
        }
        __syncthreads();
    }

#pragma unroll
    for (int i = 0; i < 8; i++) {
        const int r = row0 + ty * 4 + (i >> 2) * 64 + (i & 3);
#pragma unroll
        for (int jj = 0; jj < 2; jj++) {
            const int c = col0 + tx * 4 + jj * 64;
            if (c < N) {
                float4 o;
                o.x = acc[i][jj * 4 + 0];
                o.y = acc[i][jj * 4 + 1];
                o.z = acc[i][jj * 4 + 2];
                o.w = acc[i][jj * 4 + 3];
                *(float4*)&C[(size_t)r * N + c] = o;
            }
        }
    }
}

// ---------------------------------------------------------------------------
// Block reduction (256 threads)
// ---------------------------------------------------------------------------
__device__ __forceinline__ float block_reduce_sum_256(float v) {
    __shared__ float red[8];
    __shared__ float result;
    const int lane = threadIdx.x & 31;
    const int w = threadIdx.x >> 5;
#pragma unroll
    for (int o = 16; o > 0; o >>= 1)
        v += __shfl_xor_sync(0xffffffffu, v, o);
    if (lane == 0) red[w] = v;
    __syncthreads();
    if (threadIdx.x == 0) {
        float s = 0.f;
#pragma unroll
        for (int i = 0; i < 8; i++) s += red[i];
        result = s;
    }
    __syncthreads();
    return result;
}

// ---------------------------------------------------------------------------
// In-place RMSNorm: one block per row
// ---------------------------------------------------------------------------
__global__ __launch_bounds__(256) void rmsnorm_kernel(float* __restrict__ data, int L) {
    const size_t base = (size_t)blockIdx.x * L;
    float ss = 0.f;
    for (int i = threadIdx.x; i < L; i += 256) {
        float x = data[base + i];
        ss += x * x;
    }
    const float tot = block_reduce_sum_256(ss);
    const float r = rsqrtf(tot / (float)L + 1e-5f);
    for (int i = threadIdx.x; i < L; i += 256)
        data[base + i] *= r;
}

// ---------------------------------------------------------------------------
// kv prep: rmsnorm first 512 cols of kvdr -> kvlat ; rope last 64 -> krope
// ---------------------------------------------------------------------------
__global__ __launch_bounds__(256) void kvprep_kernel(
    const float* __restrict__ kvdr, const float* __restrict__ cosb,
    const float* __restrict__ sinb, float* __restrict__ kvlat,
    float* __restrict__ krope)
{
    const int t = blockIdx.x;
    const int s = t & (SEQ - 1);
    const float* row = kvdr + (size_t)t * 576;

    float ss = 0.f;
    for (int i = threadIdx.x; i < 512; i += 256) {
        float x = row[i];
        ss += x * x;
    }
    const float tot = block_reduce_sum_256(ss);
    const float r = rsqrtf(tot / 512.f + 1e-5f);
    for (int i = threadIdx.x; i < 512; i += 256)
        kvlat[(size_t)t * 512 + i] = row[i] * r;

    if (threadIdx.x < 32) {
        const int i = threadIdx.x;
        const float x0 = row[512 + 2 * i];
        const float x1 = row[512 + 2 * i + 1];
        const float c  = cosb[s * 32 + i];
        const float sn = sinb[s * 32 + i];
        krope[(size_t)t * 64 + 2 * i]     = x0 * c - x1 * sn;
        krope[(size_t)t * 64 + 2 * i + 1] = x0 * sn + x1 * c;
    }
}

// ---------------------------------------------------------------------------
// build q: per-head [nope128|rope64] raw -> [rope(roped)64|nope128], layout [b*H+h][s][192]
// ---------------------------------------------------------------------------
__global__ __launch_bounds__(256) void buildq_kernel(
    const float* __restrict__ qraw, const float* __restrict__ cosb,
    const float* __restrict__ sinb, float* __restrict__ gq)
{
    const int t = blockIdx.x;
    const int b = t >> 11;
    const int s = t & (SEQ - 1);
    const float* row = qraw + (size_t)t * 3072;

    // rope: 16 heads * 32 pairs
    for (int u = threadIdx.x; u < 512; u += 256) {
        const int h = u >> 5;
        const int p = u & 31;
        const float x0 = row[h * 192 + 128 + 2 * p];
        const float x1 = row[h * 192 + 128 + 2 * p + 1];
        const float c  = cosb[s * 32 + p];
        const float sn = sinb[s * 32 + p];
        const size_t o = ((size_t)(b * NH + h) * SEQ + s) * DQK;
        gq[o + 2 * p]     = x0 * c - x1 * sn;
        gq[o + 2 * p + 1] = x0 * sn + x1 * c;
    }
    // nope copy
    for (int u = threadIdx.x; u < 2048; u += 256) {
        const int h = u >> 7;
        const int j = u & 127;
        const size_t o = ((size_t)(b * NH + h) * SEQ + s) * DQK;
        gq[o + 64 + j] = row[h * 192 + j];
    }
}

// ---------------------------------------------------------------------------
// build k,v from kv up-proj + broadcast roped k_rope
// ---------------------------------------------------------------------------
__global__ __launch_bounds__(256) void buildkv_kernel(
    const float* __restrict__ kv, const float* __restrict__ krope,
    float* __restrict__ gk, float* __restrict__ gv)
{
    const int t = blockIdx.x;
    const int b = t >> 11;
    const int s = t & (SEQ - 1);
    const float* kvrow = kv + (size_t)t * 4096;
    const float* krow = krope + (size_t)t * 64;

    for (int u = threadIdx.x; u < NH * DQK; u += 256) {
        const int h = u / DQK;
        const int d = u % DQK;
        const size_t o = ((size_t)(b * NH + h) * SEQ + s) * DQK;
        gk[o + d] = (d < 64) ? krow[d] : kvrow[h * 128 + (d - 64)];
    }
    for (int u = threadIdx.x; u < NH * DV; u += 256) {
        const int h = u >> 7;
        const int j = u & 127;
        const size_t o = ((size_t)(b * NH + h) * SEQ + s) * DV;
        gv[o + j] = kvrow[2048 + h * 128 + j];
    }
}

// ---------------------------------------------------------------------------
// Flash attention (causal, fp32). BQ=BK=64, 256 threads.
// grid: (S/64, B*H)
// ---------------------------------------------------------------------------
#define QS_STRIDE 193
#define SS_STRIDE 65
#define ATTN_SMEM_FLOATS (64 * QS_STRIDE * 2 + 64 * 128 + 64 * SS_STRIDE + 3 * 64)
#define ATTN_SMEM_BYTES (ATTN_SMEM_FLOATS * 4)

__global__ __launch_bounds__(256) void attn_kernel(
    const float* __restrict__ gq, const float* __restrict__ gk,
    const float* __restrict__ gv, float* __restrict__ gout)
{
    extern __shared__ float sm[];
    float* Qs   = sm;                       // 64 x 193
    float* Ks   = Qs + 64 * QS_STRIDE;      // 64 x 193
    float* Vs   = Ks + 64 * QS_STRIDE;      // 64 x 128
    float* Ss   = Vs + 64 * 128;            // 64 x 65
    float* mrow = Ss + 64 * SS_STRIDE;      // 64
    float* lrow = mrow + 64;                // 64
    float* frow = lrow + 64;                // 64

    const int tid = threadIdx.x;
    const int tx = tid & 15;
    const int ty = tid >> 4;
    const int qt = blockIdx.x;
    const int bh = blockIdx.y;
    const int q0 = qt * 64;
    const float scale = 0.07216878364870323f;  // 1/sqrt(192)

    const size_t qk_base = (size_t)bh * SEQ * DQK;
    const size_t v_base  = (size_t)bh * SEQ * DV;

    // load Q tile
    for (int u = tid; u < 64 * 48; u += 256) {
        const int r = u / 48;
        const int c4 = (u % 48) * 4;
        const float4 v = *(const float4*)&gq[qk_base + (size_t)(q0 + r) * DQK + c4];
        Qs[r * QS_STRIDE + c4 + 0] = v.x;
        Qs[r * QS_STRIDE + c4 + 1] = v.y;
        Qs[r * QS_STRIDE + c4 + 2] = v.z;
        Qs[r * QS_STRIDE + c4 + 3] = v.w;
    }
    if (tid < 64) { mrow[tid] = -1e30f; lrow[tid] = 0.f; }

    float oacc[4][8];
#pragma unroll
    for (int i = 0; i < 4; i++)
#pragma unroll
        for (int c = 0; c < 8; c++) oacc[i][c] = 0.f;

    __syncthreads();

    for (int kt = 0; kt <= qt; kt++) {
        const int k0 = kt * 64;

        // load K tile
        for (int u = tid; u < 64 * 48; u += 256) {
            const int r = u / 48;
            const int c4 = (u % 48) * 4;
            const float4 v = *(const float4*)&gk[qk_base + (size_t)(k0 + r) * DQK + c4];
            Ks[r * QS_STRIDE + c4 + 0] = v.x;
            Ks[r * QS_STRIDE + c4 + 1] = v.y;
            Ks[r * QS_STRIDE + c4 + 2] = v.z;
            Ks[r * QS_STRIDE + c4 + 3] = v.w;
        }
        // load V tile
        for (int u = tid; u < 64 * 32; u += 256) {
            const int r = u >> 5;
            const int c4 = (u & 31) << 2;
            *(float4*)&Vs[r * 128 + c4] =
                *(const float4*)&gv[v_base + (size_t)(k0 + r) * DV + c4];
        }
        __syncthreads();

        // scores: 4x4 micro-tile per thread
        float sacc[4][4];
#pragma unroll
        for (int i = 0; i < 4; i++)
#pragma unroll
            for (int j = 0; j < 4; j++) sacc[i][j] = 0.f;

        for (int d = 0; d < DQK; d++) {
            float qv[4], kvv[4];
#pragma unroll
            for (int i = 0; i < 4; i++) qv[i] = Qs[(ty * 4 + i) * QS_STRIDE + d];
#pragma unroll
            for (int j = 0; j < 4; j++) kvv[j] = Ks[(tx * 4 + j) * QS_STRIDE + d];
#pragma unroll
            for (int i = 0; i < 4; i++)
#pragma unroll
                for (int j = 0; j < 4; j++)
                    sacc[i][j] += qv[i] * kvv[j];
        }

        const bool diag = (kt == qt);
#pragma unroll
        for (int i = 0; i < 4; i++) {
            const int gi = q0 + ty * 4 + i;
#pragma unroll
            for (int j = 0; j < 4; j++) {
                const int gj = k0 + tx * 4 + j;
                float s = sacc[i][j] * scale;
                if (diag && gj > gi) s = -1e9f;
                Ss[(ty * 4 + i) * SS_STRIDE + (tx * 4 + j)] = s;
            }
        }
        __syncthreads();

        // per-row streaming softmax update (64 rows on threads 0..63)
        if (tid < 64) {
            const int i = tid;
            const float m_old = mrow[i];
            float mx = m_old;
            for (int j = 0; j < 64; j++)
                mx = fmaxf(mx, Ss[i * SS_STRIDE + j]);
            const float f = __expf(m_old - mx);
            float s = 0.f;
            for (int j = 0; j < 64; j++) {
                const float p = __expf(Ss[i * SS_STRIDE + j] - mx);
                Ss[i * SS_STRIDE + j] = p;
                s += p;
            }
            lrow[i] = lrow[i] * f + s;
            mrow[i] = mx;
            frow[i] = f;
        }
        __syncthreads();

        // O = O*f + P @ V
#pragma unroll
        for (int i = 0; i < 4; i++) {
            const float f = frow[ty * 4 + i];
#pragma unroll
            for (int c = 0; c < 8; c++) oacc[i][c] *= f;
        }
        for (int j = 0; j < 64; j++) {
            float p[4];
#pragma unroll
            for (int i = 0; i < 4; i++) p[i] = Ss[(ty * 4 + i) * SS_STRIDE + j];
            const float4 v0 = *(const float4*)&Vs[j * 128 + tx * 4];
            const float4 v1 = *(const float4*)&Vs[j * 128 + 64 + tx * 4];
#pragma unroll
            for (int i = 0; i < 4; i++) {
                oacc[i][0] += p[i] * v0.x;
                oacc[i][1] += p[i] * v0.y;
                oacc[i][2] += p[i] * v0.z;
                oacc[i][3] += p[i] * v0.w;
                oacc[i][4] += p[i] * v1.x;
                oacc[i][5] += p[i] * v1.y;
                oacc[i][6] += p[i] * v1.z;
                oacc[i][7] += p[i] * v1.w;
            }
        }
        __syncthreads();
    }

    // epilogue: normalize and write to [token, h*128 + c]
    const int b = bh >> 4;
    const int h = bh & 15;
#pragma unroll
    for (int i = 0; i < 4; i++) {
        const int r = ty * 4 + i;
        const float inv = 1.0f / lrow[r];
        const size_t row = (size_t)(b * SEQ + q0 + r) * 2048 + h * DV;
        float4 o0, o1;
        o0.x = oacc[i][0] * inv; o0.y = oacc[i][1] * inv;
        o0.z = oacc[i][2] * inv; o0.w = oacc[i][3] * inv;
        o1.x = oacc[i][4] * inv; o1.y = oacc[i][5] * inv;
        o1.z = oacc[i][6] * inv; o1.w = oacc[i][7] * inv;
        *(float4*)&gout[row + tx * 4]      = o0;
        *(float4*)&gout[row + 64 + tx * 4] = o1;
    }
}

// ---------------------------------------------------------------------------
// launch
// ---------------------------------------------------------------------------
extern "C" void kernel_launch(void* const* d_in, const int* in_sizes, int n_in,
                              void* d_out, int out_size)
{
    const float* hidden   = (const float*)d_in[0];
    // d_in[1] = sequence_mask (all true by construction; causal mask suffices)
    const float* cosb     = (const float*)d_in[2];
    const float* sinb     = (const float*)d_in[3];
    const float* Wq_down  = (const float*)d_in[4];
    const float* Wkv_down = (const float*)d_in[5];
    const float* Wq_up    = (const float*)d_in[6];
    const float* Wkv_up   = (const float*)d_in[7];
    const float* Wo       = (const float*)d_in[8];
    float* out = (float*)d_out;

    float *qlat, *kvdr, *kvlat, *krope, *qraw, *kv, *q, *k, *v, *attn;
    cudaGetSymbolAddress((void**)&qlat,  g_qlat);
    cudaGetSymbolAddress((void**)&kvdr,  g_kvdr);
    cudaGetSymbolAddress((void**)&kvlat, g_kvlat);
    cudaGetSymbolAddress((void**)&krope, g_krope);
    cudaGetSymbolAddress((void**)&qraw,  g_qraw);
    cudaGetSymbolAddress((void**)&kv,    g_kv);
    cudaGetSymbolAddress((void**)&q,     g_q);
    cudaGetSymbolAddress((void**)&k,     g_k);
    cudaGetSymbolAddress((void**)&v,     g_v);
    cudaGetSymbolAddress((void**)&attn,  g_attn);

    cudaFuncSetAttribute(attn_kernel,
                         cudaFuncAttributeMaxDynamicSharedMemorySize,
                         ATTN_SMEM_BYTES);

    // 1. q latent = hidden @ Wq_down  [4096,2048]x[2048,1536]
    gemm_kernel<<<dim3(12, 32), 256>>>(hidden, Wq_down, qlat, TOK, 1536, 2048);
    // 2. kvdr = hidden @ Wkv_down    [4096,2048]x[2048,576]
    gemm_kernel<<<dim3(5, 32), 256>>>(hidden, Wkv_down, kvdr, TOK, 576, 2048);
    // 3. rmsnorm q latent (in place)
    rmsnorm_kernel<<<TOK, 256>>>(qlat, 1536);
    // 4. kv latent rmsnorm + k_rope rope
    kvprep_kernel<<<TOK, 256>>>(kvdr, cosb, sinb, kvlat, krope);
    // 5. q raw = qlat @ Wq_up        [4096,1536]x[1536,3072]
    gemm_kernel<<<dim3(24, 32), 256>>>(qlat, Wq_up, qraw, TOK, 3072, 1536);
    // 6. kv = kvlat @ Wkv_up         [4096,512]x[512,4096]
    gemm_kernel<<<dim3(32, 32), 256>>>(kvlat, Wkv_up, kv, TOK, 4096, 512);
    // 7. build q (rope + reorder)
    buildq_kernel<<<TOK, 256>>>(qraw, cosb, sinb, q);
    // 8. build k, v
    buildkv_kernel<<<TOK, 256>>>(kv, krope, k, v);
    // 9. flash attention
    attn_kernel<<<dim3(SEQ / 64, 2 * NH), 256, ATTN_SMEM_BYTES>>>(q, k, v, attn);
    // 10. out = attn @ Wo            [4096,2048]x[2048,2048]
    gemm_kernel<<<dim3(16, 32), 256>>>(attn, Wo, out, TOK, 2048, 2048);
}

// round 5
// speedup vs baseline: 1.6905x; 1.6905x over previous
#include <cuda_runtime.h>
#include <cuda_bf16.h>
#include <math.h>

// ---------------------------------------------------------------------------
// Problem constants: B=2, S=2048, D=2048, H=16, NOPE=128, ROPE=64, DV=128,
// DQK=192, QLR=1536, KVLR=512, tokens = 4096
// ---------------------------------------------------------------------------
#define TOK 4096
#define SEQ 2048
#define NH 16
#define DQK 192
#define DV 128

// ---------------------------------------------------------------------------
// Device scratch (static, allocation-free)
// ---------------------------------------------------------------------------
__device__ float g_qlat [4096 * 1536];
__device__ float g_kvdr [4096 * 576];
__device__ float g_kvlat[4096 * 512];
__device__ float g_krope[4096 * 64];
__device__ float g_qraw [4096L * 3072];
__device__ float g_kv   [4096L * 4096];
__device__ float g_q    [32L * 2048 * 192];
__device__ float g_k    [32L * 2048 * 192];
__device__ float g_v    [32L * 2048 * 128];
__device__ float g_attn [4096L * 2048];

// ---------------------------------------------------------------------------
// tf32 tensor-core GEMM: C[M,N] = A[M,K] @ B[K,N], row-major fp32 in/out.
// 128x128x32 tile, 256 threads (8 warps, 4x2), warp tile 32x64 (2x8 m16n8k8).
// Double-buffered dynamic smem. Requires M%128==0, K%32==0, N%4==0.
// ---------------------------------------------------------------------------
#define LDA_S 36    // A smem row stride (floats): bank = (4g+t) conflict-free
#define LDB_S 136   // B smem row stride (floats): bank = (8t+g) conflict-free
#define GEMM_SMEM_BYTES ((2 * 128 * LDA_S + 2 * 32 * LDB_S) * 4)

__device__ __forceinline__ unsigned tf32_rna(float x) {
    unsigned r;
    asm("cvt.rna.tf32.f32 %0, %1;" : "=r"(r) : "f"(x));
    return r;
}

__device__ __forceinline__ void mma_tf32(
    float* c, unsigned a0, unsigned a1, unsigned a2, unsigned a3,
    unsigned b0, unsigned b1)
{
    asm volatile(
        "mma.sync.aligned.m16n8k8.row.col.f32.tf32.tf32.f32 "
        "{%0,%1,%2,%3}, {%4,%5,%6,%7}, {%8,%9}, {%0,%1,%2,%3};\n"
        : "+f"(c[0]), "+f"(c[1]), "+f"(c[2]), "+f"(c[3])
        : "r"(a0), "r"(a1), "r"(a2), "r"(a3), "r"(b0), "r"(b1));
}

__global__ __launch_bounds__(256) void gemm_tf32_kernel(
    const float* __restrict__ A, const float* __restrict__ B,
    float* __restrict__ C, int M, int N, int K)
{
    extern __shared__ float sm[];
    float* As = sm;                      // [2][128][LDA_S]
    float* Bs = sm + 2 * 128 * LDA_S;    // [2][32][LDB_S]

    const int tid  = threadIdx.x;
    const int lane = tid & 31;
    const int warp = tid >> 5;
    const int g = lane >> 2;
    const int t = lane & 3;
    const int warp_m = (warp & 3) * 32;
    const int warp_n = (warp >> 2) * 64;
    const int row0 = blockIdx.y * 128;
    const int col0 = blockIdx.x * 128;

    // gmem load mapping
    const int ar  = tid >> 3;            // 0..31 (rows ar + p*32)
    const int ac4 = (tid & 7) * 4;       // A col within BK
    const int br  = tid >> 5;            // 0..7  (rows br + p*8)
    const int bc4 = (tid & 31) * 4;      // B col within BN

    float4 aR[4], bR[4];

    // prologue: load tile k0=0
#pragma unroll
    for (int p = 0; p < 4; p++)
        aR[p] = *(const float4*)&A[(size_t)(row0 + ar + p * 32) * K + ac4];
#pragma unroll
    for (int p = 0; p < 4; p++) {
        bR[p] = make_float4(0.f, 0.f, 0.f, 0.f);
        if (col0 + bc4 < N)
            bR[p] = *(const float4*)&B[(size_t)(br + p * 8) * N + col0 + bc4];
    }

    float acc[2][8][4];
#pragma unroll
    for (int mt = 0; mt < 2; mt++)
#pragma unroll
        for (int nt = 0; nt < 8; nt++)
#pragma unroll
            for (int i = 0; i < 4; i++) acc[mt][nt][i] = 0.f;

    // store tile 0 into buffer 0 (with tf32 rounding)
    unsigned* Asu = (unsigned*)As;
    unsigned* Bsu = (unsigned*)Bs;
#pragma unroll
    for (int p = 0; p < 4; p++) {
        const int r = ar + p * 32;
        Asu[r * LDA_S + ac4 + 0] = tf32_rna(aR[p].x);
        Asu[r * LDA_S + ac4 + 1] = tf32_rna(aR[p].y);
        Asu[r * LDA_S + ac4 + 2] = tf32_rna(aR[p].z);
        Asu[r * LDA_S + ac4 + 3] = tf32_rna(aR[p].w);
    }
#pragma unroll
    for (int p = 0; p < 4; p++) {
        const int r = br + p * 8;
        Bsu[r * LDB_S + bc4 + 0] = tf32_rna(bR[p].x);
        Bsu[r * LDB_S + bc4 + 1] = tf32_rna(bR[p].y);
        Bsu[r * LDB_S + bc4 + 2] = tf32_rna(bR[p].z);
        Bsu[r * LDB_S + bc4 + 3] = tf32_rna(bR[p].w);
    }
    __syncthreads();

    int buf = 0;
    for (int k0 = 0; k0 < K; k0 += 32) {
        const bool has_next = (k0 + 32 < K);
        if (has_next) {
#pragma unroll
            for (int p = 0; p < 4; p++)
                aR[p] = *(const float4*)&A[(size_t)(row0 + ar + p * 32) * K + k0 + 32 + ac4];
#pragma unroll
            for (int p = 0; p < 4; p++) {
                bR[p] = make_float4(0.f, 0.f, 0.f, 0.f);
                if (col0 + bc4 < N)
                    bR[p] = *(const float4*)&B[(size_t)(k0 + 32 + br + p * 8) * N + col0 + bc4];
            }
        }

        // compute on current buffer
        const unsigned* Ab = (const unsigned*)(As + buf * 128 * LDA_S);
        const unsigned* Bb = (const unsigned*)(Bs + buf * 32 * LDB_S);
#pragma unroll
        for (int kk = 0; kk < 4; kk++) {
            const int kc = kk * 8;
            unsigned a[2][4];
#pragma unroll
            for (int mt = 0; mt < 2; mt++) {
                const int r = warp_m + mt * 16 + g;
                a[mt][0] = Ab[(r)     * LDA_S + kc + t];
                a[mt][1] = Ab[(r + 8) * LDA_S + kc + t];
                a[mt][2] = Ab[(r)     * LDA_S + kc + t + 4];
                a[mt][3] = Ab[(r + 8) * LDA_S + kc + t + 4];
            }
#pragma unroll
            for (int nt = 0; nt < 8; nt++) {
                const int c = warp_n + nt * 8 + g;
                const unsigned b0 = Bb[(kc + t)     * LDB_S + c];
                const unsigned b1 = Bb[(kc + t + 4) * LDB_S + c];
                mma_tf32(acc[0][nt], a[0][0], a[0][1], a[0][2], a[0][3], b0, b1);
                mma_tf32(acc[1][nt], a[1][0], a[1][1], a[1][2], a[1][3], b0, b1);
            }
        }

        if (has_next) {
            const int nb = buf ^ 1;
            unsigned* An = (unsigned*)(As + nb * 128 * LDA_S);
            unsigned* Bn = (unsigned*)(Bs + nb * 32 * LDB_S);
#pragma unroll
            for (int p = 0; p < 4; p++) {
                const int r = ar + p * 32;
                An[r * LDA_S + ac4 + 0] = tf32_rna(aR[p].x);
                An[r * LDA_S + ac4 + 1] = tf32_rna(aR[p].y);
                An[r * LDA_S + ac4 + 2] = tf32_rna(aR[p].z);
                An[r * LDA_S + ac4 + 3] = tf32_rna(aR[p].w);
            }
#pragma unroll
            for (int p = 0; p < 4; p++) {
                const int r = br + p * 8;
                Bn[r * LDB_S + bc4 + 0] = tf32_rna(bR[p].x);
                Bn[r * LDB_S + bc4 + 1] = tf32_rna(bR[p].y);
                Bn[r * LDB_S + bc4 + 2] = tf32_rna(bR[p].z);
                Bn[r * LDB_S + bc4 + 3] = tf32_rna(bR[p].w);
            }
            __syncthreads();
            buf = nb;
        }
    }

    // epilogue: c0/c1 at (row, 2t), (row, 2t+1); c2/c3 at row+8
#pragma unroll
    for (int mt = 0; mt < 2; mt++) {
#pragma unroll
        for (int nt = 0; nt < 8; nt++) {
            const int c = col0 + warp_n + nt * 8 + 2 * t;
            if (c < N) {
                const int r = row0 + warp_m + mt * 16 + g;
                float2 v0 = make_float2(acc[mt][nt][0], acc[mt][nt][1]);
                float2 v1 = make_float2(acc[mt][nt][2], acc[mt][nt][3]);
                *(float2*)&C[(size_t)r * N + c] = v0;
                *(float2*)&C[(size_t)(r + 8) * N + c] = v1;
            }
        }
    }
}

// ---------------------------------------------------------------------------
// Block reduction (256 threads)
// ---------------------------------------------------------------------------
__device__ __forceinline__ float block_reduce_sum_256(float v) {
    __shared__ float red[8];
    __shared__ float result;
    const int lane = threadIdx.x & 31;
    const int w = threadIdx.x >> 5;
#pragma unroll
    for (int o = 16; o > 0; o >>= 1)
        v += __shfl_xor_sync(0xffffffffu, v, o);
    if (lane == 0) red[w] = v;
    __syncthreads();
    if (threadIdx.x == 0) {
        float s = 0.f;
#pragma unroll
        for (int i = 0; i < 8; i++) s += red[i];
        result = s;
    }
    __syncthreads();
    return result;
}

__global__ __launch_bounds__(256) void rmsnorm_kernel(float* __restrict__ data, int L) {
    const size_t base = (size_t)blockIdx.x * L;
    float ss = 0.f;
    for (int i = threadIdx.x; i < L; i += 256) {
        float x = data[base + i];
        ss += x * x;
    }
    const float tot = block_reduce_sum_256(ss);
    const float r = rsqrtf(tot / (float)L + 1e-5f);
    for (int i = threadIdx.x; i < L; i += 256)
        data[base + i] *= r;
}

__global__ __launch_bounds__(256) void kvprep_kernel(
    const float* __restrict__ kvdr, const float* __restrict__ cosb,
    const float* __restrict__ sinb, float* __restrict__ kvlat,
    float* __restrict__ krope)
{
    const int t = blockIdx.x;
    const int s = t & (SEQ - 1);
    const float* row = kvdr + (size_t)t * 576;

    float ss = 0.f;
    for (int i = threadIdx.x; i < 512; i += 256) {
        float x = row[i];
        ss += x * x;
    }
    const float tot = block_reduce_sum_256(ss);
    const float r = rsqrtf(tot / 512.f + 1e-5f);
    for (int i = threadIdx.x; i < 512; i += 256)
        kvlat[(size_t)t * 512 + i] = row[i] * r;

    if (threadIdx.x < 32) {
        const int i = threadIdx.x;
        const float x0 = row[512 + 2 * i];
        const float x1 = row[512 + 2 * i + 1];
        const float c  = cosb[s * 32 + i];
        const float sn = sinb[s * 32 + i];
        krope[(size_t)t * 64 + 2 * i]     = x0 * c - x1 * sn;
        krope[(size_t)t * 64 + 2 * i + 1] = x0 * sn + x1 * c;
    }
}

__global__ __launch_bounds__(256) void buildq_kernel(
    const float* __restrict__ qraw, const float* __restrict__ cosb,
    const float* __restrict__ sinb, float* __restrict__ gq)
{
    const int t = blockIdx.x;
    const int b = t >> 11;
    const int s = t & (SEQ - 1);
    const float* row = qraw + (size_t)t * 3072;

    for (int u = threadIdx.x; u < 512; u += 256) {
        const int h = u >> 5;
        const int p = u & 31;
        const float x0 = row[h * 192 + 128 + 2 * p];
        const float x1 = row[h * 192 + 128 + 2 * p + 1];
        const float c  = cosb[s * 32 + p];
        const float sn = sinb[s * 32 + p];
        const size_t o = ((size_t)(b * NH + h) * SEQ + s) * DQK;
        gq[o + 2 * p]     = x0 * c - x1 * sn;
        gq[o + 2 * p + 1] = x0 * sn + x1 * c;
    }
    for (int u = threadIdx.x; u < 2048; u += 256) {
        const int h = u >> 7;
        const int j = u & 127;
        const size_t o = ((size_t)(b * NH + h) * SEQ + s) * DQK;
        gq[o + 64 + j] = row[h * 192 + j];
    }
}

__global__ __launch_bounds__(256) void buildkv_kernel(
    const float* __restrict__ kv, const float* __restrict__ krope,
    float* __restrict__ gk, float* __restrict__ gv)
{
    const int t = blockIdx.x;
    const int b = t >> 11;
    const int s = t & (SEQ - 1);
    const float* kvrow = kv + (size_t)t * 4096;
    const float* krow = krope + (size_t)t * 64;

    for (int u = threadIdx.x; u < NH * DQK; u += 256) {
        const int h = u / DQK;
        const int d = u % DQK;
        const size_t o = ((size_t)(b * NH + h) * SEQ + s) * DQK;
        gk[o + d] = (d < 64) ? krow[d] : kvrow[h * 128 + (d - 64)];
    }
    for (int u = threadIdx.x; u < NH * DV; u += 256) {
        const int h = u >> 7;
        const int j = u & 127;
        const size_t o = ((size_t)(b * NH + h) * SEQ + s) * DV;
        gv[o + j] = kvrow[2048 + h * 128 + j];
    }
}

// ---------------------------------------------------------------------------
// Flash attention (causal, fp32). BQ=BK=64, 256 threads. grid: (S/64, B*H)
// ---------------------------------------------------------------------------
#define QS_STRIDE 193
#define SS_STRIDE 65
#define ATTN_SMEM_FLOATS (64 * QS_STRIDE * 2 + 64 * 128 + 64 * SS_STRIDE + 3 * 64)
#define ATTN_SMEM_BYTES (ATTN_SMEM_FLOATS * 4)

__global__ __launch_bounds__(256) void attn_kernel(
    const float* __restrict__ gq, const float* __restrict__ gk,
    const float* __restrict__ gv, float* __restrict__ gout)
{
    extern __shared__ float sm[];
    float* Qs   = sm;
    float* Ks   = Qs + 64 * QS_STRIDE;
    float* Vs   = Ks + 64 * QS_STRIDE;
    float* Ss   = Vs + 64 * 128;
    float* mrow = Ss + 64 * SS_STRIDE;
    float* lrow = mrow + 64;
    float* frow = lrow + 64;

    const int tid = threadIdx.x;
    const int tx = tid & 15;
    const int ty = tid >> 4;
    const int qt = blockIdx.x;
    const int bh = blockIdx.y;
    const int q0 = qt * 64;
    const float scale = 0.07216878364870323f;

    const size_t qk_base = (size_t)bh * SEQ * DQK;
    const size_t v_base  = (size_t)bh * SEQ * DV;

    for (int u = tid; u < 64 * 48; u += 256) {
        const int r = u / 48;
        const int c4 = (u % 48) * 4;
        const float4 v = *(const float4*)&gq[qk_base + (size_t)(q0 + r) * DQK + c4];
        Qs[r * QS_STRIDE + c4 + 0] = v.x;
        Qs[r * QS_STRIDE + c4 + 1] = v.y;
        Qs[r * QS_STRIDE + c4 + 2] = v.z;
        Qs[r * QS_STRIDE + c4 + 3] = v.w;
    }
    if (tid < 64) { mrow[tid] = -1e30f; lrow[tid] = 0.f; }

    float oacc[4][8];
#pragma unroll
    for (int i = 0; i < 4; i++)
#pragma unroll
        for (int c = 0; c < 8; c++) oacc[i][c] = 0.f;

    __syncthreads();

    for (int kt = 0; kt <= qt; kt++) {
        const int k0 = kt * 64;

        for (int u = tid; u < 64 * 48; u += 256) {
            const int r = u / 48;
            const int c4 = (u % 48) * 4;
            const float4 v = *(const float4*)&gk[qk_base + (size_t)(k0 + r) * DQK + c4];
            Ks[r * QS_STRIDE + c4 + 0] = v.x;
            Ks[r * QS_STRIDE + c4 + 1] = v.y;
            Ks[r * QS_STRIDE + c4 + 2] = v.z;
            Ks[r * QS_STRIDE + c4 + 3] = v.w;
        }
        for (int u = tid; u < 64 * 32; u += 256) {
            const int r = u >> 5;
            const int c4 = (u & 31) << 2;
            *(float4*)&Vs[r * 128 + c4] =
                *(const float4*)&gv[v_base + (size_t)(k0 + r) * DV + c4];
        }
        __syncthreads();

        float sacc[4][4];
#pragma unroll
        for (int i = 0; i < 4; i++)
#pragma unroll
            for (int j = 0; j < 4; j++) sacc[i][j] = 0.f;

        for (int d = 0; d < DQK; d++) {
            float qv[4], kvv[4];
#pragma unroll
            for (int i = 0; i < 4; i++) qv[i] = Qs[(ty * 4 + i) * QS_STRIDE + d];
#pragma unroll
            for (int j = 0; j < 4; j++) kvv[j] = Ks[(tx * 4 + j) * QS_STRIDE + d];
#pragma unroll
            for (int i = 0; i < 4; i++)
#pragma unroll
                for (int j = 0; j < 4; j++)
                    sacc[i][j] += qv[i] * kvv[j];
        }

        const bool diag = (kt == qt);
#pragma unroll
        for (int i = 0; i < 4; i++) {
            const int gi = q0 + ty * 4 + i;
#pragma unroll
            for (int j = 0; j < 4; j++) {
                const int gj = k0 + tx * 4 + j;
                float s = sacc[i][j] * scale;
                if (diag && gj > gi) s = -1e9f;
                Ss[(ty * 4 + i) * SS_STRIDE + (tx * 4 + j)] = s;
            }
        }
        __syncthreads();

        if (tid < 64) {
            const int i = tid;
            const float m_old = mrow[i];
            float mx = m_old;
            for (int j = 0; j < 64; j++)
                mx = fmaxf(mx, Ss[i * SS_STRIDE + j]);
            const float f = __expf(m_old - mx);
            float s = 0.f;
            for (int j = 0; j < 64; j++) {
                const float p = __expf(Ss[i * SS_STRIDE + j] - mx);
                Ss[i * SS_STRIDE + j] = p;
                s += p;
            }
            lrow[i] = lrow[i] * f + s;
            mrow[i] = mx;
            frow[i] = f;
        }
        __syncthreads();

#pragma unroll
        for (int i = 0; i < 4; i++) {
            const float f = frow[ty * 4 + i];
#pragma unroll
            for (int c = 0; c < 8; c++) oacc[i][c] *= f;
        }
        for (int j = 0; j < 64; j++) {
            float p[4];
#pragma unroll
            for (int i = 0; i < 4; i++) p[i] = Ss[(ty * 4 + i) * SS_STRIDE + j];
            const float4 v0 = *(const float4*)&Vs[j * 128 + tx * 4];
            const float4 v1 = *(const float4*)&Vs[j * 128 + 64 + tx * 4];
#pragma unroll
            for (int i = 0; i < 4; i++) {
                oacc[i][0] += p[i] * v0.x;
                oacc[i][1] += p[i] * v0.y;
                oacc[i][2] += p[i] * v0.z;
                oacc[i][3] += p[i] * v0.w;
                oacc[i][4] += p[i] * v1.x;
                oacc[i][5] += p[i] * v1.y;
                oacc[i][6] += p[i] * v1.z;
                oacc[i][7] += p[i] * v1.w;
            }
        }
        __syncthreads();
    }

    const int b = bh >> 4;
    const int h = bh & 15;
#pragma unroll
    for (int i = 0; i < 4; i++) {
        const int r = ty * 4 + i;
        const float inv = 1.0f / lrow[r];
        const size_t row = (size_t)(b * SEQ + q0 + r) * 2048 + h * DV;
        float4 o0, o1;
        o0.x = oacc[i][0] * inv; o0.y = oacc[i][1] * inv;
        o0.z = oacc[i][2] * inv; o0.w = oacc[i][3] * inv;
        o1.x = oacc[i][4] * inv; o1.y = oacc[i][5] * inv;
        o1.z = oacc[i][6] * inv; o1.w = oacc[i][7] * inv;
        *(float4*)&gout[row + tx * 4]      = o0;
        *(float4*)&gout[row + 64 + tx * 4] = o1;
    }
}

// ---------------------------------------------------------------------------
// launch
// ---------------------------------------------------------------------------
extern "C" void kernel_launch(void* const* d_in, const int* in_sizes, int n_in,
                              void* d_out, int out_size)
{
    const float* hidden   = (const float*)d_in[0];
    const float* cosb     = (const float*)d_in[2];
    const float* sinb     = (const float*)d_in[3];
    const float* Wq_down  = (const float*)d_in[4];
    const float* Wkv_down = (const float*)d_in[5];
    const float* Wq_up    = (const float*)d_in[6];
    const float* Wkv_up   = (const float*)d_in[7];
    const float* Wo       = (const float*)d_in[8];
    float* out = (float*)d_out;

    float *qlat, *kvdr, *kvlat, *krope, *qraw, *kv, *q, *k, *v, *attn;
    cudaGetSymbolAddress((void**)&qlat,  g_qlat);
    cudaGetSymbolAddress((void**)&kvdr,  g_kvdr);
    cudaGetSymbolAddress((void**)&kvlat, g_kvlat);
    cudaGetSymbolAddress((void**)&krope, g_krope);
    cudaGetSymbolAddress((void**)&qraw,  g_qraw);
    cudaGetSymbolAddress((void**)&kv,    g_kv);
    cudaGetSymbolAddress((void**)&q,     g_q);
    cudaGetSymbolAddress((void**)&k,     g_k);
    cudaGetSymbolAddress((void**)&v,     g_v);
    cudaGetSymbolAddress((void**)&attn,  g_attn);

    cudaFuncSetAttribute(attn_kernel,
                         cudaFuncAttributeMaxDynamicSharedMemorySize,
                         ATTN_SMEM_BYTES);
    cudaFuncSetAttribute(gemm_tf32_kernel,
                         cudaFuncAttributeMaxDynamicSharedMemorySize,
                         GEMM_SMEM_BYTES);

    // 1. q latent = hidden @ Wq_down
    gemm_tf32_kernel<<<dim3(12, 32), 256, GEMM_SMEM_BYTES>>>(hidden, Wq_down, qlat, TOK, 1536, 2048);
    // 2. kvdr = hidden @ Wkv_down
    gemm_tf32_kernel<<<dim3(5, 32), 256, GEMM_SMEM_BYTES>>>(hidden, Wkv_down, kvdr, TOK, 576, 2048);
    // 3. rmsnorm q latent
    rmsnorm_kernel<<<TOK, 256>>>(qlat, 1536);
    // 4. kv latent rmsnorm + k_rope rope
    kvprep_kernel<<<TOK, 256>>>(kvdr, cosb, sinb, kvlat, krope);
    // 5. q raw = qlat @ Wq_up
    gemm_tf32_kernel<<<dim3(24, 32), 256, GEMM_SMEM_BYTES>>>(qlat, Wq_up, qraw, TOK, 3072, 1536);
    // 6. kv = kvlat @ Wkv_up
    gemm_tf32_kernel<<<dim3(32, 32), 256, GEMM_SMEM_BYTES>>>(kvlat, Wkv_up, kv, TOK, 4096, 512);
    // 7. build q
    buildq_kernel<<<TOK, 256>>>(qraw, cosb, sinb, q);
    // 8. build k, v
    buildkv_kernel<<<TOK, 256>>>(kv, krope, k, v);
    // 9. flash attention
    attn_kernel<<<dim3(SEQ / 64, 2 * NH), 256, ATTN_SMEM_BYTES>>>(q, k, v, attn);
    // 10. out = attn @ Wo
    gemm_tf32_kernel<<<dim3(16, 32), 256, GEMM_SMEM_BYTES>>>(attn, Wo, out, TOK, 2048, 2048);
}

// round 7
// speedup vs baseline: 2.3685x; 1.4010x over previous
#include <cuda_runtime.h>
#include <cuda_bf16.h>
#include <math.h>

// ---------------------------------------------------------------------------
// Problem constants: B=2, S=2048, D=2048, H=16, NOPE=128, ROPE=64, DV=128,
// DQK=192, QLR=1536, KVLR=512, tokens = 4096
// ---------------------------------------------------------------------------
#define TOK 4096
#define SEQ 2048
#define NH 16
#define DQK 192
#define DV 128

// ---------------------------------------------------------------------------
// Device scratch (static, allocation-free)
// ---------------------------------------------------------------------------
__device__ float g_qlat [4096 * 1536];
__device__ float g_kvdr [4096 * 576];
__device__ float g_kvlat[4096 * 512];
__device__ float g_krope[4096 * 64];
__device__ float g_qraw [4096L * 3072];
__device__ float g_kv   [4096L * 4096];
__device__ float g_q    [32L * 2048 * 192];
__device__ float g_k    [32L * 2048 * 192];
__device__ float g_v    [32L * 2048 * 128];
__device__ float g_attn [4096L * 2048];

__device__ __forceinline__ unsigned tf32_rna(float x) {
    unsigned r;
    asm("cvt.rna.tf32.f32 %0, %1;" : "=r"(r) : "f"(x));
    return r;
}

__device__ __forceinline__ void mma_tf32(
    float* c, unsigned a0, unsigned a1, unsigned a2, unsigned a3,
    unsigned b0, unsigned b1)
{
    asm volatile(
        "mma.sync.aligned.m16n8k8.row.col.f32.tf32.tf32.f32 "
        "{%0,%1,%2,%3}, {%4,%5,%6,%7}, {%8,%9}, {%0,%1,%2,%3};\n"
        : "+f"(c[0]), "+f"(c[1]), "+f"(c[2]), "+f"(c[3])
        : "r"(a0), "r"(a1), "r"(a2), "r"(a3), "r"(b0), "r"(b1));
}

// ---------------------------------------------------------------------------
// tf32 tensor-core GEMM (unchanged from R5, it works): C = A@B row-major.
// ---------------------------------------------------------------------------
#define LDA_S 36
#define LDB_S 136
#define GEMM_SMEM_BYTES ((2 * 128 * LDA_S + 2 * 32 * LDB_S) * 4)

__global__ __launch_bounds__(256) void gemm_tf32_kernel(
    const float* __restrict__ A, const float* __restrict__ B,
    float* __restrict__ C, int M, int N, int K)
{
    extern __shared__ float sm[];
    float* As = sm;
    float* Bs = sm + 2 * 128 * LDA_S;

    const int tid  = threadIdx.x;
    const int lane = tid & 31;
    const int warp = tid >> 5;
    const int g = lane >> 2;
    const int t = lane & 3;
    const int warp_m = (warp & 3) * 32;
    const int warp_n = (warp >> 2) * 64;
    const int row0 = blockIdx.y * 128;
    const int col0 = blockIdx.x * 128;

    const int ar  = tid >> 3;
    const int ac4 = (tid & 7) * 4;
    const int br  = tid >> 5;
    const int bc4 = (tid & 31) * 4;

    float4 aR[4], bR[4];

#pragma unroll
    for (int p = 0; p < 4; p++)
        aR[p] = *(const float4*)&A[(size_t)(row0 + ar + p * 32) * K + ac4];
#pragma unroll
    for (int p = 0; p < 4; p++) {
        bR[p] = make_float4(0.f, 0.f, 0.f, 0.f);
        if (col0 + bc4 < N)
            bR[p] = *(const float4*)&B[(size_t)(br + p * 8) * N + col0 + bc4];
    }

    float acc[2][8][4];
#pragma unroll
    for (int mt = 0; mt < 2; mt++)
#pragma unroll
        for (int nt = 0; nt < 8; nt++)
#pragma unroll
            for (int i = 0; i < 4; i++) acc[mt][nt][i] = 0.f;

    unsigned* Asu = (unsigned*)As;
    unsigned* Bsu = (unsigned*)Bs;
#pragma unroll
    for (int p = 0; p < 4; p++) {
        const int r = ar + p * 32;
        Asu[r * LDA_S + ac4 + 0] = tf32_rna(aR[p].x);
        Asu[r * LDA_S + ac4 + 1] = tf32_rna(aR[p].y);
        Asu[r * LDA_S + ac4 + 2] = tf32_rna(aR[p].z);
        Asu[r * LDA_S + ac4 + 3] = tf32_rna(aR[p].w);
    }
#pragma unroll
    for (int p = 0; p < 4; p++) {
        const int r = br + p * 8;
        Bsu[r * LDB_S + bc4 + 0] = tf32_rna(bR[p].x);
        Bsu[r * LDB_S + bc4 + 1] = tf32_rna(bR[p].y);
        Bsu[r * LDB_S + bc4 + 2] = tf32_rna(bR[p].z);
        Bsu[r * LDB_S + bc4 + 3] = tf32_rna(bR[p].w);
    }
    __syncthreads();

    int buf = 0;
    for (int k0 = 0; k0 < K; k0 += 32) {
        const bool has_next = (k0 + 32 < K);
        if (has_next) {
#pragma unroll
            for (int p = 0; p < 4; p++)
                aR[p] = *(const float4*)&A[(size_t)(row0 + ar + p * 32) * K + k0 + 32 + ac4];
#pragma unroll
            for (int p = 0; p < 4; p++) {
                bR[p] = make_float4(0.f, 0.f, 0.f, 0.f);
                if (col0 + bc4 < N)
                    bR[p] = *(const float4*)&B[(size_t)(k0 + 32 + br + p * 8) * N + col0 + bc4];
            }
        }

        const unsigned* Ab = (const unsigned*)(As + buf * 128 * LDA_S);
        const unsigned* Bb = (const unsigned*)(Bs + buf * 32 * LDB_S);
#pragma unroll
        for (int kk = 0; kk < 4; kk++) {
            const int kc = kk * 8;
            unsigned a[2][4];
#pragma unroll
            for (int mt = 0; mt < 2; mt++) {
                const int r = warp_m + mt * 16 + g;
                a[mt][0] = Ab[(r)     * LDA_S + kc + t];
                a[mt][1] = Ab[(r + 8) * LDA_S + kc + t];
                a[mt][2] = Ab[(r)     * LDA_S + kc + t + 4];
                a[mt][3] = Ab[(r + 8) * LDA_S + kc + t + 4];
            }
#pragma unroll
            for (int nt = 0; nt < 8; nt++) {
                const int c = warp_n + nt * 8 + g;
                const unsigned b0 = Bb[(kc + t)     * LDB_S + c];
                const unsigned b1 = Bb[(kc + t + 4) * LDB_S + c];
                mma_tf32(acc[0][nt], a[0][0], a[0][1], a[0][2], a[0][3], b0, b1);
                mma_tf32(acc[1][nt], a[1][0], a[1][1], a[1][2], a[1][3], b0, b1);
            }
        }

        if (has_next) {
            const int nb = buf ^ 1;
            unsigned* An = (unsigned*)(As + nb * 128 * LDA_S);
            unsigned* Bn = (unsigned*)(Bs + nb * 32 * LDB_S);
#pragma unroll
            for (int p = 0; p < 4; p++) {
                const int r = ar + p * 32;
                An[r * LDA_S + ac4 + 0] = tf32_rna(aR[p].x);
                An[r * LDA_S + ac4 + 1] = tf32_rna(aR[p].y);
                An[r * LDA_S + ac4 + 2] = tf32_rna(aR[p].z);
                An[r * LDA_S + ac4 + 3] = tf32_rna(aR[p].w);
            }
#pragma unroll
            for (int p = 0; p < 4; p++) {
                const int r = br + p * 8;
                Bn[r * LDB_S + bc4 + 0] = tf32_rna(bR[p].x);
                Bn[r * LDB_S + bc4 + 1] = tf32_rna(bR[p].y);
                Bn[r * LDB_S + bc4 + 2] = tf32_rna(bR[p].z);
                Bn[r * LDB_S + bc4 + 3] = tf32_rna(bR[p].w);
            }
            __syncthreads();
            buf = nb;
        }
    }

#pragma unroll
    for (int mt = 0; mt < 2; mt++) {
#pragma unroll
        for (int nt = 0; nt < 8; nt++) {
            const int c = col0 + warp_n + nt * 8 + 2 * t;
            if (c < N) {
                const int r = row0 + warp_m + mt * 16 + g;
                float2 v0 = make_float2(acc[mt][nt][0], acc[mt][nt][1]);
                float2 v1 = make_float2(acc[mt][nt][2], acc[mt][nt][3]);
                *(float2*)&C[(size_t)r * N + c] = v0;
                *(float2*)&C[(size_t)(r + 8) * N + c] = v1;
            }
        }
    }
}

// ---------------------------------------------------------------------------
// Block reduction & elementwise kernels (unchanged)
// ---------------------------------------------------------------------------
__device__ __forceinline__ float block_reduce_sum_256(float v) {
    __shared__ float red[8];
    __shared__ float result;
    const int lane = threadIdx.x & 31;
    const int w = threadIdx.x >> 5;
#pragma unroll
    for (int o = 16; o > 0; o >>= 1)
        v += __shfl_xor_sync(0xffffffffu, v, o);
    if (lane == 0) red[w] = v;
    __syncthreads();
    if (threadIdx.x == 0) {
        float s = 0.f;
#pragma unroll
        for (int i = 0; i < 8; i++) s += red[i];
        result = s;
    }
    __syncthreads();
    return result;
}

__global__ __launch_bounds__(256) void rmsnorm_kernel(float* __restrict__ data, int L) {
    const size_t base = (size_t)blockIdx.x * L;
    float ss = 0.f;
    for (int i = threadIdx.x; i < L; i += 256) {
        float x = data[base + i];
        ss += x * x;
    }
    const float tot = block_reduce_sum_256(ss);
    const float r = rsqrtf(tot / (float)L + 1e-5f);
    for (int i = threadIdx.x; i < L; i += 256)
        data[base + i] *= r;
}

__global__ __launch_bounds__(256) void kvprep_kernel(
    const float* __restrict__ kvdr, const float* __restrict__ cosb,
    const float* __restrict__ sinb, float* __restrict__ kvlat,
    float* __restrict__ krope)
{
    const int t = blockIdx.x;
    const int s = t & (SEQ - 1);
    const float* row = kvdr + (size_t)t * 576;

    float ss = 0.f;
    for (int i = threadIdx.x; i < 512; i += 256) {
        float x = row[i];
        ss += x * x;
    }
    const float tot = block_reduce_sum_256(ss);
    const float r = rsqrtf(tot / 512.f + 1e-5f);
    for (int i = threadIdx.x; i < 512; i += 256)
        kvlat[(size_t)t * 512 + i] = row[i] * r;

    if (threadIdx.x < 32) {
        const int i = threadIdx.x;
        const float x0 = row[512 + 2 * i];
        const float x1 = row[512 + 2 * i + 1];
        const float c  = cosb[s * 32 + i];
        const float sn = sinb[s * 32 + i];
        krope[(size_t)t * 64 + 2 * i]     = x0 * c - x1 * sn;
        krope[(size_t)t * 64 + 2 * i + 1] = x0 * sn + x1 * c;
    }
}

__global__ __launch_bounds__(256) void buildq_kernel(
    const float* __restrict__ qraw, const float* __restrict__ cosb,
    const float* __restrict__ sinb, float* __restrict__ gq)
{
    const int t = blockIdx.x;
    const int b = t >> 11;
    const int s = t & (SEQ - 1);
    const float* row = qraw + (size_t)t * 3072;

    for (int u = threadIdx.x; u < 512; u += 256) {
        const int h = u >> 5;
        const int p = u & 31;
        const float x0 = row[h * 192 + 128 + 2 * p];
        const float x1 = row[h * 192 + 128 + 2 * p + 1];
        const float c  = cosb[s * 32 + p];
        const float sn = sinb[s * 32 + p];
        const size_t o = ((size_t)(b * NH + h) * SEQ + s) * DQK;
        gq[o + 2 * p]     = x0 * c - x1 * sn;
        gq[o + 2 * p + 1] = x0 * sn + x1 * c;
    }
    for (int u = threadIdx.x; u < 2048; u += 256) {
        const int h = u >> 7;
        const int j = u & 127;
        const size_t o = ((size_t)(b * NH + h) * SEQ + s) * DQK;
        gq[o + 64 + j] = row[h * 192 + j];
    }
}

__global__ __launch_bounds__(256) void buildkv_kernel(
    const float* __restrict__ kv, const float* __restrict__ krope,
    float* __restrict__ gk, float* __restrict__ gv)
{
    const int t = blockIdx.x;
    const int b = t >> 11;
    const int s = t & (SEQ - 1);
    const float* kvrow = kv + (size_t)t * 4096;
    const float* krow = krope + (size_t)t * 64;

    for (int u = threadIdx.x; u < NH * DQK; u += 256) {
        const int h = u / DQK;
        const int d = u % DQK;
        const size_t o = ((size_t)(b * NH + h) * SEQ + s) * DQK;
        gk[o + d] = (d < 64) ? krow[d] : kvrow[h * 128 + (d - 64)];
    }
    for (int u = threadIdx.x; u < NH * DV; u += 256) {
        const int h = u >> 7;
        const int j = u & 127;
        const size_t o = ((size_t)(b * NH + h) * SEQ + s) * DV;
        gv[o + j] = kvrow[2048 + h * 128 + j];
    }
}

// ---------------------------------------------------------------------------
// Tensor-core flash attention (causal). BQ=BK=64, 256 threads (8 warps, 4x2).
// tf32 MMA for QK^T and P@V; fp32 online softmax (warp-per-8-rows).
// Smem strides chosen for conflict-free fragment loads:
//   Q/K stride 196 (==4 mod 32 -> bank 4g+t), V stride 136 (bank 8t+g),
//   S/P stride 68 (==4 mod 32).
// ---------------------------------------------------------------------------
#define AQ_S 196
#define AV_S 136
#define AS_S 68
#define ATTN_SMEM_FLOATS (2 * 64 * AQ_S + 64 * AV_S + 64 * AS_S + 3 * 64)
#define ATTN_SMEM_BYTES (ATTN_SMEM_FLOATS * 4)

__global__ __launch_bounds__(256) void attn_tc_kernel(
    const float* __restrict__ gq, const float* __restrict__ gk,
    const float* __restrict__ gv, float* __restrict__ gout)
{
    extern __shared__ float sm[];
    unsigned* Qs = (unsigned*)sm;            // 64 x AQ_S (tf32 bits)
    unsigned* Ks = Qs + 64 * AQ_S;           // 64 x AQ_S
    unsigned* Vs = Ks + 64 * AQ_S;           // 64 x AV_S
    float* Ss    = (float*)(Vs + 64 * AV_S); // 64 x AS_S (scores fp32 / P tf32)
    float* mrow  = Ss + 64 * AS_S;
    float* lrow  = mrow + 64;
    float* frow  = lrow + 64;

    const int tid  = threadIdx.x;
    const int lane = tid & 31;
    const int warp = tid >> 5;
    const int g = lane >> 2;
    const int t = lane & 3;
    const int warp_m  = (warp & 3) * 16;     // 16-row block per warp
    const int warp_nS = (warp >> 2) * 32;    // S: 32-col half
    const int warp_nO = (warp >> 2) * 64;    // O: 64-col half
    const int qt = blockIdx.x;
    const int bh = blockIdx.y;
    const int q0 = qt * 64;
    const float scale = 0.07216878364870323f; // 1/sqrt(192)

    const size_t qk_base = (size_t)bh * SEQ * DQK;
    const size_t v_base  = (size_t)bh * SEQ * DV;

    // load Q tile -> tf32 smem
    for (int u = tid; u < 64 * 48; u += 256) {
        const int r = u / 48;
        const int c4 = (u % 48) * 4;
        const float4 v = *(const float4*)&gq[qk_base + (size_t)(q0 + r) * DQK + c4];
        Qs[r * AQ_S + c4 + 0] = tf32_rna(v.x);
        Qs[r * AQ_S + c4 + 1] = tf32_rna(v.y);
        Qs[r * AQ_S + c4 + 2] = tf32_rna(v.z);
        Qs[r * AQ_S + c4 + 3] = tf32_rna(v.w);
    }
    if (tid < 64) { mrow[tid] = -1e30f; lrow[tid] = 0.f; }

    float oacc[8][4];
#pragma unroll
    for (int nt = 0; nt < 8; nt++)
#pragma unroll
        for (int i = 0; i < 4; i++) oacc[nt][i] = 0.f;

    __syncthreads();

    for (int kt = 0; kt <= qt; kt++) {
        const int k0 = kt * 64;

        // load K, V tiles -> tf32 smem
        for (int u = tid; u < 64 * 48; u += 256) {
            const int r = u / 48;
            const int c4 = (u % 48) * 4;
            const float4 v = *(const float4*)&gk[qk_base + (size_t)(k0 + r) * DQK + c4];
            Ks[r * AQ_S + c4 + 0] = tf32_rna(v.x);
            Ks[r * AQ_S + c4 + 1] = tf32_rna(v.y);
            Ks[r * AQ_S + c4 + 2] = tf32_rna(v.z);
            Ks[r * AQ_S + c4 + 3] = tf32_rna(v.w);
        }
        for (int u = tid; u < 64 * 32; u += 256) {
            const int r = u >> 5;
            const int c4 = (u & 31) << 2;
            const float4 v = *(const float4*)&gv[v_base + (size_t)(k0 + r) * DV + c4];
            Vs[r * AV_S + c4 + 0] = tf32_rna(v.x);
            Vs[r * AV_S + c4 + 1] = tf32_rna(v.y);
            Vs[r * AV_S + c4 + 2] = tf32_rna(v.z);
            Vs[r * AV_S + c4 + 3] = tf32_rna(v.w);
        }
        __syncthreads();

        // --- S = Q @ K^T via mma (warp: 16 x 32) ---
        float sacc[4][4];
#pragma unroll
        for (int nt = 0; nt < 4; nt++)
#pragma unroll
            for (int i = 0; i < 4; i++) sacc[nt][i] = 0.f;

#pragma unroll
        for (int ks = 0; ks < 24; ks++) {
            const int kc = ks * 8;
            const unsigned a0 = Qs[(warp_m + g)     * AQ_S + kc + t];
            const unsigned a1 = Qs[(warp_m + g + 8) * AQ_S + kc + t];
            const unsigned a2 = Qs[(warp_m + g)     * AQ_S + kc + t + 4];
            const unsigned a3 = Qs[(warp_m + g + 8) * AQ_S + kc + t + 4];
#pragma unroll
            for (int nt = 0; nt < 4; nt++) {
                const int n = warp_nS + nt * 8 + g;
                const unsigned b0 = Ks[n * AQ_S + kc + t];
                const unsigned b1 = Ks[n * AQ_S + kc + t + 4];
                mma_tf32(sacc[nt], a0, a1, a2, a3, b0, b1);
            }
        }

        // scale + causal mask + write scores to smem
        const bool diag = (kt == qt);
#pragma unroll
        for (int nt = 0; nt < 4; nt++) {
            const int col = warp_nS + nt * 8 + 2 * t;
            const int r0 = warp_m + g;
            const int r1 = r0 + 8;
            float s00 = sacc[nt][0] * scale, s01 = sacc[nt][1] * scale;
            float s10 = sacc[nt][2] * scale, s11 = sacc[nt][3] * scale;
            if (diag) {
                const int gi0 = q0 + r0, gi1 = q0 + r1;
                const int gj0 = k0 + col, gj1 = gj0 + 1;
                if (gj0 > gi0) s00 = -1e9f;
                if (gj1 > gi0) s01 = -1e9f;
                if (gj0 > gi1) s10 = -1e9f;
                if (gj1 > gi1) s11 = -1e9f;
            }
            *(float2*)&Ss[r0 * AS_S + col] = make_float2(s00, s01);
            *(float2*)&Ss[r1 * AS_S + col] = make_float2(s10, s11);
        }
        __syncthreads();

        // --- online softmax: warp w owns rows w*8 .. w*8+7 ---
#pragma unroll
        for (int rr = 0; rr < 8; rr++) {
            const int i = warp * 8 + rr;
            const float x0 = Ss[i * AS_S + lane];
            const float x1 = Ss[i * AS_S + lane + 32];
            float mx = fmaxf(x0, x1);
#pragma unroll
            for (int o = 16; o > 0; o >>= 1)
                mx = fmaxf(mx, __shfl_xor_sync(0xffffffffu, mx, o));
            const float mold = mrow[i];
            const float mnew = fmaxf(mold, mx);
            const float p0 = __expf(x0 - mnew);
            const float p1 = __expf(x1 - mnew);
            float s = p0 + p1;
#pragma unroll
            for (int o = 16; o > 0; o >>= 1)
                s += __shfl_xor_sync(0xffffffffu, s, o);
            ((unsigned*)Ss)[i * AS_S + lane]      = tf32_rna(p0);
            ((unsigned*)Ss)[i * AS_S + lane + 32] = tf32_rna(p1);
            if (lane == 0) {
                const float f = __expf(mold - mnew);
                lrow[i] = lrow[i] * f + s;
                mrow[i] = mnew;
                frow[i] = f;
            }
        }
        __syncthreads();

        // --- O = O * f + P @ V via mma (warp: 16 x 64) ---
        const float f0 = frow[warp_m + g];
        const float f1 = frow[warp_m + g + 8];
#pragma unroll
        for (int nt = 0; nt < 8; nt++) {
            oacc[nt][0] *= f0; oacc[nt][1] *= f0;
            oacc[nt][2] *= f1; oacc[nt][3] *= f1;
        }
        const unsigned* Psu = (const unsigned*)Ss;
#pragma unroll
        for (int ks = 0; ks < 8; ks++) {
            const int kc = ks * 8;
            const unsigned a0 = Psu[(warp_m + g)     * AS_S + kc + t];
            const unsigned a1 = Psu[(warp_m + g + 8) * AS_S + kc + t];
            const unsigned a2 = Psu[(warp_m + g)     * AS_S + kc + t + 4];
            const unsigned a3 = Psu[(warp_m + g + 8) * AS_S + kc + t + 4];
#pragma unroll
            for (int nt = 0; nt < 8; nt++) {
                const int col = warp_nO + nt * 8 + g;
                const unsigned b0 = Vs[(kc + t)     * AV_S + col];
                const unsigned b1 = Vs[(kc + t + 4) * AV_S + col];
                mma_tf32(oacc[nt], a0, a1, a2, a3, b0, b1);
            }
        }
        __syncthreads();
    }

    // epilogue: normalize, write to [token, h*128 + col]
    const int b = bh >> 4;
    const int h = bh & 15;
    const float inv0 = 1.0f / lrow[warp_m + g];
    const float inv1 = 1.0f / lrow[warp_m + g + 8];
    const size_t row0 = (size_t)(b * SEQ + q0 + warp_m + g) * 2048 + h * DV;
    const size_t row1 = row0 + 8 * 2048;
#pragma unroll
    for (int nt = 0; nt < 8; nt++) {
        const int col = warp_nO + nt * 8 + 2 * t;
        *(float2*)&gout[row0 + col] =
            make_float2(oacc[nt][0] * inv0, oacc[nt][1] * inv0);
        *(float2*)&gout[row1 + col] =
            make_float2(oacc[nt][2] * inv1, oacc[nt][3] * inv1);
    }
}

// ---------------------------------------------------------------------------
// launch
// ---------------------------------------------------------------------------
extern "C" void kernel_launch(void* const* d_in, const int* in_sizes, int n_in,
                              void* d_out, int out_size)
{
    const float* hidden   = (const float*)d_in[0];
    const float* cosb     = (const float*)d_in[2];
    const float* sinb     = (const float*)d_in[3];
    const float* Wq_down  = (const float*)d_in[4];
    const float* Wkv_down = (const float*)d_in[5];
    const float* Wq_up    = (const float*)d_in[6];
    const float* Wkv_up   = (const float*)d_in[7];
    const float* Wo       = (const float*)d_in[8];
    float* out = (float*)d_out;

    float *qlat, *kvdr, *kvlat, *krope, *qraw, *kv, *q, *k, *v, *attn;
    cudaGetSymbolAddress((void**)&qlat,  g_qlat);
    cudaGetSymbolAddress((void**)&kvdr,  g_kvdr);
    cudaGetSymbolAddress((void**)&kvlat, g_kvlat);
    cudaGetSymbolAddress((void**)&krope, g_krope);
    cudaGetSymbolAddress((void**)&qraw,  g_qraw);
    cudaGetSymbolAddress((void**)&kv,    g_kv);
    cudaGetSymbolAddress((void**)&q,     g_q);
    cudaGetSymbolAddress((void**)&k,     g_k);
    cudaGetSymbolAddress((void**)&v,     g_v);
    cudaGetSymbolAddress((void**)&attn,  g_attn);

    cudaFuncSetAttribute(attn_tc_kernel,
                         cudaFuncAttributeMaxDynamicSharedMemorySize,
                         ATTN_SMEM_BYTES);
    cudaFuncSetAttribute(gemm_tf32_kernel,
                         cudaFuncAttributeMaxDynamicSharedMemorySize,
                         GEMM_SMEM_BYTES);

    // 1. q latent = hidden @ Wq_down
    gemm_tf32_kernel<<<dim3(12, 32), 256, GEMM_SMEM_BYTES>>>(hidden, Wq_down, qlat, TOK, 1536, 2048);
    // 2. kvdr = hidden @ Wkv_down
    gemm_tf32_kernel<<<dim3(5, 32), 256, GEMM_SMEM_BYTES>>>(hidden, Wkv_down, kvdr, TOK, 576, 2048);
    // 3. rmsnorm q latent
    rmsnorm_kernel<<<TOK, 256>>>(qlat, 1536);
    // 4. kv latent rmsnorm + k_rope rope
    kvprep_kernel<<<TOK, 256>>>(kvdr, cosb, sinb, kvlat, krope);
    // 5. q raw = qlat @ Wq_up
    gemm_tf32_kernel<<<dim3(24, 32), 256, GEMM_SMEM_BYTES>>>(qlat, Wq_up, qraw, TOK, 3072, 1536);
    // 6. kv = kvlat @ Wkv_up
    gemm_tf32_kernel<<<dim3(32, 32), 256, GEMM_SMEM_BYTES>>>(kvlat, Wkv_up, kv, TOK, 4096, 512);
    // 7. build q
    buildq_kernel<<<TOK, 256>>>(qraw, cosb, sinb, q);
    // 8. build k, v
    buildkv_kernel<<<TOK, 256>>>(kv, krope, k, v);
    // 9. tensor-core flash attention
    attn_tc_kernel<<<dim3(SEQ / 64, 2 * NH), 256, ATTN_SMEM_BYTES>>>(q, k, v, attn);
    // 10. out = attn @ Wo
    gemm_tf32_kernel<<<dim3(16, 32), 256, GEMM_SMEM_BYTES>>>(attn, Wo, out, TOK, 2048, 2048);
}